// round 4
// baseline (speedup 1.0000x reference)
#include <cuda_runtime.h>
#include <math.h>

#define BB 4
#define LQ 128
#define LF 64
#define NW 2
#define NFR 8
#define EE 128
#define DD 128
#define VV 64
#define WF (NW*NFR)   // 16

// ---- output layout (concatenated in reference tuple order) ----
#define OUT_FRAGCODE  0                               // (B,NW,NFR,D)   = 8192
#define OUT_QUERYCODE (BB*WF*DD)                      // (B,NW,NFR,D)   = 8192
#define OUT_SELFATT   (2*BB*WF*DD)                    // (B,NW,NFR,LF)  = 4096
#define OUT_GATE      (2*BB*WF*DD + BB*WF*LF)         // (B,WF,LQ)      = 8192
#define OUT_QUERY    (OUT_GATE + BB*WF*LQ)            // (B,LQ,E)       = 65536

// ---- scratch ----
__device__ float g_fproj[BB*WF*LF*DD];   // projected fragment (b,wf,lf,d)
__device__ float g_qatt [BB*LQ*VV];      // q_att (b,lq,v)
__device__ float g_fatt [BB*WF*LF*VV];   // f_att (b,wf,lf,v)
__device__ float g_e2   [BB*WF*LQ];      // exp(qf@val_w)*mask
__device__ float g_pmax [1024*32*64];    // partial maxes: [bwf][lqt][lfq][32][64] (8MB)

// ============================================================
// Kernel A: projection (query rows then fragment rows), GEMM+bias.
// (the all-zero-row mask in _project is a mathematical no-op)
// ============================================================
__global__ void k_proj(const float* __restrict__ query,
                       const float* __restrict__ frag,
                       const float* __restrict__ W,
                       const float* __restrict__ bias,
                       float* __restrict__ outq) {
    int row = blockIdx.x;
    int j = threadIdx.x;      // 0..127
    __shared__ float xsh[EE];
    const float* src = (row < BB*LQ) ? (query + (size_t)row*EE)
                                     : (frag  + (size_t)(row - BB*LQ)*EE);
    xsh[j] = src[j];
    __syncthreads();
    float acc = bias[j];
    #pragma unroll 8
    for (int d = 0; d < EE; d++) acc = fmaf(xsh[d], W[d*DD + j], acc);
    float* dst = (row < BB*LQ) ? (outq + (size_t)row*DD)
                               : (g_fproj + (size_t)(row - BB*LQ)*DD);
    dst[j] = acc;
}

// ============================================================
// Kernel B: fragment self-attention softmax + frag_code
// ============================================================
__global__ void k_fragcode(const float* __restrict__ saW,
                           const float* __restrict__ fmask,
                           float* __restrict__ out) {
    int bwf = blockIdx.x;                 // 0..63  (b*WF + wf)
    int w = (bwf % WF) / NFR;
    const float* fbase = g_fproj + (size_t)bwf*LF*DD;
    __shared__ float att[LF];
    __shared__ float s_inv;
    int t = threadIdx.x;                  // 128 threads
    if (t < LF) {
        const float* fr = fbase + t*DD;
        const float* sw = saW + w*DD;
        float acc = 0.f;
        #pragma unroll 8
        for (int d = 0; d < DD; d++) acc += fr[d]*sw[d];
        att[t] = expf(acc) * fmask[bwf*LF + t];
    }
    __syncthreads();
    if (t == 0) {
        float s = 0.f;
        for (int l = 0; l < LF; l++) s += att[l];
        s_inv = 1.f / (s + 1e-7f);
    }
    __syncthreads();
    float inv = s_inv;
    if (t < LF) out[OUT_SELFATT + bwf*LF + t] = att[t]*inv;
    float acc = 0.f;
    #pragma unroll 8
    for (int l = 0; l < LF; l++) acc += att[l]*inv*fbase[l*DD + t];
    out[OUT_FRAGCODE + bwf*DD + t] = acc;
}

// ============================================================
// Kernel C: q_att = q @ q_att_W, f_att = f @ f_att_W
// ============================================================
__global__ void k_att(const float* __restrict__ outq,
                      const float* __restrict__ qW,
                      const float* __restrict__ fW) {
    int row = blockIdx.x;
    int j = threadIdx.x;      // 0..63
    __shared__ float xsh[DD];
    const float* src; const float* W; float* dst;
    if (row < BB*LQ) { src = outq + (size_t)row*DD;            W = qW; dst = g_qatt + (size_t)row*VV; }
    else             { int r = row - BB*LQ;
                       src = g_fproj + (size_t)r*DD;           W = fW; dst = g_fatt + (size_t)r*VV; }
    xsh[j] = src[j]; xsh[j+64] = src[j+64];
    __syncthreads();
    float acc = 0.f;
    #pragma unroll 8
    for (int d = 0; d < DD; d++) acc = fmaf(xsh[d], W[d*VV + j], acc);
    dst[j] = acc;
}

// ============================================================
// Kernel D (hot): per (b,wf, lq-tile32, lf-quarter16): partial max over lf of
//   (f_att + (q ⊙ f_lf) @ W_qf), scalar FFMA, 128 threads.
// Each thread owns 2(lq) x 8(v); v ownership {4g..4g+3, 32+4g..32+4g+3}
// so each W LDS.128 phase covers one contiguous 128B line (conflict-free).
// Writes a 32x64 partial-max tile to g_pmax.
// ============================================================
__global__ void __launch_bounds__(128) k_qf(const float* __restrict__ qfW,
                                            const float* __restrict__ outq) {
    extern __shared__ float sh[];
    float* Wsh    = sh;                 // 128*64 = 8192 floats
    float* qsh    = sh + 8192;          // 32*132 = 4224
    float* qfs    = sh + 12416;         // 32*132 = 4224
    float* fsh    = sh + 16640;         // 128
    float* fattsh = sh + 16768;         // 64

    int blk = blockIdx.x;               // 1024 = bwf(64) x lqt(4) x lfq(4)
    int lfq = blk & 3;
    int lqt = (blk >> 2) & 3;
    int bwf = blk >> 4;
    int b   = bwf >> 4;                 // WF = 16
    int lqbase = lqt * 32;
    int lfbase = lfq * 16;
    int tid = threadIdx.x;              // 0..127
    int g  = tid & 7;
    int l0 = (tid >> 3) * 2;            // 0,2,..,30
    int vA = 4*g;
    int vB = 32 + 4*g;

    // stage W_qf (8192 floats = 2048 float4): 16 per thread
    {
        const float4* Wv = (const float4*)qfW;
        float4* Ws = (float4*)Wsh;
        #pragma unroll
        for (int i = 0; i < 16; i++) Ws[tid + 128*i] = Wv[tid + 128*i];
    }
    // stage q tile (32 x 128), smem row stride 132
    {
        int r = tid >> 2, seg = tid & 3;              // row, 32-float segment
        const float4* qr = (const float4*)(outq + (size_t)(b*LQ + lqbase + r)*DD + seg*32);
        float4* qd = (float4*)(qsh + r*132 + seg*32);
        #pragma unroll
        for (int i = 0; i < 8; i++) qd[i] = qr[i];
    }

    float m[2][8];
    #pragma unroll
    for (int i = 0; i < 2; i++)
        #pragma unroll
        for (int j = 0; j < 8; j++) m[i][j] = -INFINITY;

    for (int lf = lfbase; lf < lfbase + 16; lf++) {
        __syncthreads();
        const float* fptr = g_fproj + ((size_t)bwf*LF + lf)*DD;
        if (tid < 128) fsh[tid] = fptr[tid];
        if (tid < 64)  fattsh[tid] = g_fatt[((size_t)bwf*LF + lf)*VV + tid];
        __syncthreads();

        // qfs = q (*) f  (elementwise along d), vectorized, 8 float4/thread
        {
            int r = tid >> 2, seg = tid & 3;
            const float4* qd = (const float4*)(qsh + r*132 + seg*32);
            const float4* fh = (const float4*)(fsh + seg*32);
            float4* od = (float4*)(qfs + r*132 + seg*32);
            #pragma unroll
            for (int i = 0; i < 8; i++) {
                float4 q = qd[i];
                float4 f = fh[i];
                od[i] = make_float4(q.x*f.x, q.y*f.y, q.z*f.z, q.w*f.w);
            }
        }
        __syncthreads();

        float acc[2][8];
        #pragma unroll
        for (int i = 0; i < 2; i++)
            #pragma unroll
            for (int j = 0; j < 8; j++) acc[i][j] = 0.f;

        const float* q0 = qfs + (l0+0)*132;
        const float* q1 = qfs + (l0+1)*132;

        #pragma unroll 4
        for (int d = 0; d < DD; d++) {
            float4 w0 = *(const float4*)(Wsh + d*VV + vA);
            float4 w1 = *(const float4*)(Wsh + d*VV + vB);
            float a0 = q0[d];
            float a1 = q1[d];
            acc[0][0] = fmaf(a0, w0.x, acc[0][0]); acc[0][1] = fmaf(a0, w0.y, acc[0][1]);
            acc[0][2] = fmaf(a0, w0.z, acc[0][2]); acc[0][3] = fmaf(a0, w0.w, acc[0][3]);
            acc[0][4] = fmaf(a0, w1.x, acc[0][4]); acc[0][5] = fmaf(a0, w1.y, acc[0][5]);
            acc[0][6] = fmaf(a0, w1.z, acc[0][6]); acc[0][7] = fmaf(a0, w1.w, acc[0][7]);
            acc[1][0] = fmaf(a1, w0.x, acc[1][0]); acc[1][1] = fmaf(a1, w0.y, acc[1][1]);
            acc[1][2] = fmaf(a1, w0.z, acc[1][2]); acc[1][3] = fmaf(a1, w0.w, acc[1][3]);
            acc[1][4] = fmaf(a1, w1.x, acc[1][4]); acc[1][5] = fmaf(a1, w1.y, acc[1][5]);
            acc[1][6] = fmaf(a1, w1.z, acc[1][6]); acc[1][7] = fmaf(a1, w1.w, acc[1][7]);
        }

        // running max of (acc + f_att)
        float4 fA = *(const float4*)&fattsh[vA];
        float4 fB = *(const float4*)&fattsh[vB];
        #pragma unroll
        for (int i = 0; i < 2; i++) {
            m[i][0] = fmaxf(m[i][0], acc[i][0] + fA.x);
            m[i][1] = fmaxf(m[i][1], acc[i][1] + fA.y);
            m[i][2] = fmaxf(m[i][2], acc[i][2] + fA.z);
            m[i][3] = fmaxf(m[i][3], acc[i][3] + fA.w);
            m[i][4] = fmaxf(m[i][4], acc[i][4] + fB.x);
            m[i][5] = fmaxf(m[i][5], acc[i][5] + fB.y);
            m[i][6] = fmaxf(m[i][6], acc[i][6] + fB.z);
            m[i][7] = fmaxf(m[i][7], acc[i][7] + fB.w);
        }
    }

    // write partial-max tile [32][64]
    float* outp = g_pmax + (size_t)blk * 2048;
    #pragma unroll
    for (int i = 0; i < 2; i++) {
        *(float4*)&outp[(l0+i)*64 + vA] = make_float4(m[i][0], m[i][1], m[i][2], m[i][3]);
        *(float4*)&outp[(l0+i)*64 + vB] = make_float4(m[i][4], m[i][5], m[i][6], m[i][7]);
    }
}

// ============================================================
// Kernel D2: combine 4 lf-quarter partial maxes, add q_att,
// gate/val dots, sigmoid/exp.
// ============================================================
__global__ void k_qfin(const float* __restrict__ gate_w,
                       const float* __restrict__ val_w,
                       const float* __restrict__ qmask,
                       float* __restrict__ out) {
    int blk = blockIdx.x;          // 256 = bwf(64) x lqt(4)
    int lqt = blk & 3;
    int bwf = blk >> 2;
    int b   = bwf >> 4;
    int lqbase = lqt * 32;
    int tid = threadIdx.x;         // 0..63
    int g  = tid & 7;
    int l0 = (tid >> 3) * 4;
    int vA = 4*g, vB = 32 + 4*g;

    float4 gwA = *(const float4*)&gate_w[vA];
    float4 gwB = *(const float4*)&gate_w[vB];
    float4 vwA = *(const float4*)&val_w[vA];
    float4 vwB = *(const float4*)&val_w[vB];

    const float* base = g_pmax + (size_t)blk * 4 * 2048;

    #pragma unroll
    for (int i = 0; i < 4; i++) {
        int row = l0 + i;
        float4 mA = *(const float4*)&base[row*64 + vA];
        float4 mB = *(const float4*)&base[row*64 + vB];
        #pragma unroll
        for (int q = 1; q < 4; q++) {
            float4 a = *(const float4*)&base[q*2048 + row*64 + vA];
            float4 bq = *(const float4*)&base[q*2048 + row*64 + vB];
            mA.x = fmaxf(mA.x, a.x);  mA.y = fmaxf(mA.y, a.y);
            mA.z = fmaxf(mA.z, a.z);  mA.w = fmaxf(mA.w, a.w);
            mB.x = fmaxf(mB.x, bq.x); mB.y = fmaxf(mB.y, bq.y);
            mB.z = fmaxf(mB.z, bq.z); mB.w = fmaxf(mB.w, bq.w);
        }
        int lq = lqbase + row;
        const float* qa = g_qatt + (size_t)(b*LQ + lq)*VV;
        float4 qaA = *(const float4*)&qa[vA];
        float4 qaB = *(const float4*)&qa[vB];
        mA.x += qaA.x; mA.y += qaA.y; mA.z += qaA.z; mA.w += qaA.w;
        mB.x += qaB.x; mB.y += qaB.y; mB.z += qaB.z; mB.w += qaB.w;

        float gs = mA.x*gwA.x + mA.y*gwA.y + mA.z*gwA.z + mA.w*gwA.w
                 + mB.x*gwB.x + mB.y*gwB.y + mB.z*gwB.z + mB.w*gwB.w;
        float vs = mA.x*vwA.x + mA.y*vwA.y + mA.z*vwA.z + mA.w*vwA.w
                 + mB.x*vwB.x + mB.y*vwB.y + mB.z*vwB.z + mB.w*vwB.w;
        #pragma unroll
        for (int off = 4; off >= 1; off >>= 1) {
            gs += __shfl_down_sync(0xffffffffu, gs, off, 8);
            vs += __shfl_down_sync(0xffffffffu, vs, off, 8);
        }
        if (g == 0) {
            float qm = qmask[b*LQ + lq];
            out[OUT_GATE + bwf*LQ + lq] = (1.f / (1.f + expf(-gs))) * qm;
            g_e2[bwf*LQ + lq] = expf(vs) * qm;
        }
    }
}

// ============================================================
// Kernel E: normalize e2 over LQ, query_code = sum_lq norm*q
// ============================================================
__global__ void k_qcode(const float* __restrict__ outq,
                        float* __restrict__ out) {
    int bwf = blockIdx.x;       // 0..63
    int b = bwf / WF;
    int t = threadIdx.x;        // 0..127 (d)
    __shared__ float esh[LQ];
    __shared__ float s_inv;
    esh[t] = g_e2[bwf*LQ + t];
    __syncthreads();
    if (t == 0) {
        float s = 0.f;
        for (int l = 0; l < LQ; l++) s += esh[l];
        s_inv = 1.f / (s + 1e-7f);
    }
    __syncthreads();
    float inv = s_inv;
    float acc = 0.f;
    #pragma unroll 8
    for (int l = 0; l < LQ; l++) acc += esh[l] * outq[((size_t)(b*LQ + l))*DD + t];
    out[OUT_QUERYCODE + bwf*DD + t] = acc * inv;
}

// ============================================================
extern "C" void kernel_launch(void* const* d_in, const int* in_sizes, int n_in,
                              void* d_out, int out_size) {
    const float* query    = (const float*)d_in[0];
    const float* fragment = (const float*)d_in[1];
    const float* qmask    = (const float*)d_in[2];
    const float* fmask    = (const float*)d_in[3];
    const float* projW    = (const float*)d_in[4];
    const float* projb    = (const float*)d_in[5];
    const float* saW      = (const float*)d_in[6];
    const float* qattW    = (const float*)d_in[7];
    const float* fattW    = (const float*)d_in[8];
    const float* qfW      = (const float*)d_in[9];
    const float* gatew    = (const float*)d_in[10];
    const float* valw     = (const float*)d_in[11];
    float* out = (float*)d_out;

    const int nrows = BB*LQ + BB*WF*LF;   // 4608

    const int smem = 16832 * (int)sizeof(float);   // 67328 B
    cudaFuncSetAttribute(k_qf, cudaFuncAttributeMaxDynamicSharedMemorySize, smem);

    k_proj<<<nrows, 128>>>(query, fragment, projW, projb, out + OUT_QUERY);
    k_fragcode<<<BB*WF, 128>>>(saW, fmask, out);
    k_att<<<nrows, 64>>>(out + OUT_QUERY, qattW, fattW);

    k_qf<<<1024, 128, smem>>>(qfW, out + OUT_QUERY);

    k_qfin<<<BB*WF*4, 64>>>(gatew, valw, qmask, out);
    k_qcode<<<BB*WF, 128>>>(out + OUT_QUERY, out);
}

// round 5
// speedup vs baseline: 2.3391x; 2.3391x over previous
#include <cuda_runtime.h>
#include <math.h>

#define BB 4
#define LQ 128
#define LF 64
#define NW 2
#define NFR 8
#define EE 128
#define DD 128
#define VV 64
#define WF (NW*NFR)   // 16

// ---- output layout (concatenated in reference tuple order) ----
#define OUT_FRAGCODE  0                               // (B,NW,NFR,D)   = 8192
#define OUT_QUERYCODE (BB*WF*DD)                      // (B,NW,NFR,D)   = 8192
#define OUT_SELFATT   (2*BB*WF*DD)                    // (B,NW,NFR,LF)  = 4096
#define OUT_GATE      (2*BB*WF*DD + BB*WF*LF)         // (B,WF,LQ)      = 8192
#define OUT_QUERY    (OUT_GATE + BB*WF*LQ)            // (B,LQ,E)       = 65536

// ---- scratch ----
__device__ float g_fproj[BB*WF*LF*DD];   // projected fragment (b,wf,lf,d)
__device__ float g_qatt [BB*LQ*VV];      // q_att (b,lq,v)
__device__ float g_fatt [BB*WF*LF*VV];   // f_att (b,wf,lf,v)
__device__ float g_e2   [BB*WF*LQ];      // exp(qf@val_w)*mask
__device__ float g_pmax [1024*32*64];    // partial maxes: [bwf][lqt][lfq][32][64] (8MB)

// packed fp32x2 helpers (Blackwell FFMA2 path)
#define FMA2(acc, a, b) asm("fma.rn.f32x2 %0, %1, %2, %0;" : "+l"(acc) : "l"(a), "l"(b))

__device__ __forceinline__ unsigned long long bcast2(float a) {
    unsigned long long r;
    asm("mov.b64 %0, {%1, %1};" : "=l"(r) : "f"(a));
    return r;
}
__device__ __forceinline__ float2 unpack2(unsigned long long u) {
    float2 r;
    asm("mov.b64 {%0, %1}, %2;" : "=f"(r.x), "=f"(r.y) : "l"(u));
    return r;
}

// ============================================================
// Kernel A: projection (query rows then fragment rows), GEMM+bias.
// (the all-zero-row mask in _project is a mathematical no-op)
// ============================================================
__global__ void k_proj(const float* __restrict__ query,
                       const float* __restrict__ frag,
                       const float* __restrict__ W,
                       const float* __restrict__ bias,
                       float* __restrict__ outq) {
    int row = blockIdx.x;
    int j = threadIdx.x;      // 0..127
    __shared__ float xsh[EE];
    const float* src = (row < BB*LQ) ? (query + (size_t)row*EE)
                                     : (frag  + (size_t)(row - BB*LQ)*EE);
    xsh[j] = src[j];
    __syncthreads();
    float acc = bias[j];
    #pragma unroll 8
    for (int d = 0; d < EE; d++) acc = fmaf(xsh[d], W[d*DD + j], acc);
    float* dst = (row < BB*LQ) ? (outq + (size_t)row*DD)
                               : (g_fproj + (size_t)(row - BB*LQ)*DD);
    dst[j] = acc;
}

// ============================================================
// Kernel B: fragment self-attention softmax + frag_code
// ============================================================
__global__ void k_fragcode(const float* __restrict__ saW,
                           const float* __restrict__ fmask,
                           float* __restrict__ out) {
    int bwf = blockIdx.x;                 // 0..63  (b*WF + wf)
    int w = (bwf % WF) / NFR;
    const float* fbase = g_fproj + (size_t)bwf*LF*DD;
    __shared__ float att[LF];
    __shared__ float s_inv;
    int t = threadIdx.x;                  // 128 threads
    if (t < LF) {
        const float* fr = fbase + t*DD;
        const float* sw = saW + w*DD;
        float acc = 0.f;
        #pragma unroll 8
        for (int d = 0; d < DD; d++) acc += fr[d]*sw[d];
        att[t] = expf(acc) * fmask[bwf*LF + t];
    }
    __syncthreads();
    if (t == 0) {
        float s = 0.f;
        for (int l = 0; l < LF; l++) s += att[l];
        s_inv = 1.f / (s + 1e-7f);
    }
    __syncthreads();
    float inv = s_inv;
    if (t < LF) out[OUT_SELFATT + bwf*LF + t] = att[t]*inv;
    float acc = 0.f;
    #pragma unroll 8
    for (int l = 0; l < LF; l++) acc += att[l]*inv*fbase[l*DD + t];
    out[OUT_FRAGCODE + bwf*DD + t] = acc;
}

// ============================================================
// Kernel C: q_att = q @ q_att_W, f_att = f @ f_att_W
// ============================================================
__global__ void k_att(const float* __restrict__ outq,
                      const float* __restrict__ qW,
                      const float* __restrict__ fW) {
    int row = blockIdx.x;
    int j = threadIdx.x;      // 0..63
    __shared__ float xsh[DD];
    const float* src; const float* W; float* dst;
    if (row < BB*LQ) { src = outq + (size_t)row*DD;            W = qW; dst = g_qatt + (size_t)row*VV; }
    else             { int r = row - BB*LQ;
                       src = g_fproj + (size_t)r*DD;           W = fW; dst = g_fatt + (size_t)r*VV; }
    xsh[j] = src[j]; xsh[j+64] = src[j+64];
    __syncthreads();
    float acc = 0.f;
    #pragma unroll 8
    for (int d = 0; d < DD; d++) acc = fmaf(xsh[d], W[d*VV + j], acc);
    dst[j] = acc;
}

// ============================================================
// Kernel D (hot): per (b,wf, lq-tile32, lf-quarter16): partial max over lf of
//   (f_att + (q ⊙ f_lf) @ W_qf).
// lf-blocked by 4 (W smem reads amortized over 4 lf) + packed f32x2 FMAs.
// 128 threads; thread owns 2(lq) x 8(v) x 4(lf) accumulators.
// v ownership {4g..4g+3, 32+4g..32+4g+3} -> conflict-free LDS.128 on W.
// Writes a 32x64 partial-max tile to g_pmax.
// ============================================================
__global__ void __launch_bounds__(128) k_qf(const float* __restrict__ qfW,
                                            const float* __restrict__ outq) {
    extern __shared__ float sh[];
    float* Wsh    = sh;                 // 128*64 = 8192 floats
    float* qsh    = sh + 8192;          // 32*132 = 4224
    float* fsh2   = sh + 12416;         // 4*128  = 512   (chunk of 4 f rows)
    float* fattsh = sh + 12928;         // 4*64   = 256
    // total 13184 floats = 52736 B

    int blk = blockIdx.x;               // 1024 = bwf(64) x lqt(4) x lfq(4)
    int lfq = blk & 3;
    int lqt = (blk >> 2) & 3;
    int bwf = blk >> 4;
    int b   = bwf >> 4;                 // WF = 16
    int lqbase = lqt * 32;
    int lfbase = lfq * 16;
    int tid = threadIdx.x;              // 0..127
    int g  = tid & 7;
    int l0 = (tid >> 3) * 2;            // 0,2,..,30
    int vA = 4*g;
    int vB = 32 + 4*g;

    // stage W_qf (8192 floats = 2048 float4): 16 per thread
    {
        const float4* Wv = (const float4*)qfW;
        float4* Ws = (float4*)Wsh;
        #pragma unroll
        for (int i = 0; i < 16; i++) Ws[tid + 128*i] = Wv[tid + 128*i];
    }
    // stage q tile (32 x 128), smem row stride 132
    {
        int r = tid >> 2, seg = tid & 3;              // row, 32-float segment
        const float4* qr = (const float4*)(outq + (size_t)(b*LQ + lqbase + r)*DD + seg*32);
        float4* qd = (float4*)(qsh + r*132 + seg*32);
        #pragma unroll
        for (int i = 0; i < 8; i++) qd[i] = qr[i];
    }

    float m[2][8];
    #pragma unroll
    for (int i = 0; i < 2; i++)
        #pragma unroll
        for (int j = 0; j < 8; j++) m[i][j] = -INFINITY;

    const float* q0p = qsh + (l0+0)*132;
    const float* q1p = qsh + (l0+1)*132;

    for (int c = 0; c < 4; c++) {                 // 4 chunks of 4 lf
        int lf0 = lfbase + c*4;
        __syncthreads();
        // stage 4 f rows (4*128) and 4 f_att rows (4*64)
        {
            const float* fp = g_fproj + ((size_t)bwf*LF + lf0)*DD;
            #pragma unroll
            for (int l = 0; l < 4; l++) fsh2[l*128 + tid] = fp[l*DD + tid];
            const float* fa = g_fatt + ((size_t)bwf*LF + lf0)*VV;
            fattsh[tid] = fa[tid];
            fattsh[tid + 128] = fa[tid + 128];
        }
        __syncthreads();

        // accumulators: [lf 4][lq 2][v-pair 4] packed f32x2
        unsigned long long acc[4][2][4];
        #pragma unroll
        for (int l = 0; l < 4; l++)
            #pragma unroll
            for (int i = 0; i < 2; i++)
                #pragma unroll
                for (int j = 0; j < 4; j++) acc[l][i][j] = 0ull;

        #pragma unroll 2
        for (int d = 0; d < DD; d++) {
            ulonglong2 w0 = *(const ulonglong2*)(Wsh + d*VV + vA);
            ulonglong2 w1 = *(const ulonglong2*)(Wsh + d*VV + vB);
            float q0 = q0p[d];
            float q1 = q1p[d];
            #pragma unroll
            for (int l = 0; l < 4; l++) {
                float f = fsh2[l*128 + d];
                unsigned long long a0 = bcast2(f*q0);
                unsigned long long a1 = bcast2(f*q1);
                FMA2(acc[l][0][0], a0, w0.x); FMA2(acc[l][0][1], a0, w0.y);
                FMA2(acc[l][0][2], a0, w1.x); FMA2(acc[l][0][3], a0, w1.y);
                FMA2(acc[l][1][0], a1, w0.x); FMA2(acc[l][1][1], a1, w0.y);
                FMA2(acc[l][1][2], a1, w1.x); FMA2(acc[l][1][3], a1, w1.y);
            }
        }

        // running max of (acc + f_att) over the 4 lf
        #pragma unroll
        for (int l = 0; l < 4; l++) {
            float4 fA = *(const float4*)&fattsh[l*64 + vA];
            float4 fB = *(const float4*)&fattsh[l*64 + vB];
            #pragma unroll
            for (int i = 0; i < 2; i++) {
                float2 p;
                p = unpack2(acc[l][i][0]);
                m[i][0] = fmaxf(m[i][0], p.x + fA.x);
                m[i][1] = fmaxf(m[i][1], p.y + fA.y);
                p = unpack2(acc[l][i][1]);
                m[i][2] = fmaxf(m[i][2], p.x + fA.z);
                m[i][3] = fmaxf(m[i][3], p.y + fA.w);
                p = unpack2(acc[l][i][2]);
                m[i][4] = fmaxf(m[i][4], p.x + fB.x);
                m[i][5] = fmaxf(m[i][5], p.y + fB.y);
                p = unpack2(acc[l][i][3]);
                m[i][6] = fmaxf(m[i][6], p.x + fB.z);
                m[i][7] = fmaxf(m[i][7], p.y + fB.w);
            }
        }
    }

    // write partial-max tile [32][64]
    float* outp = g_pmax + (size_t)blk * 2048;
    #pragma unroll
    for (int i = 0; i < 2; i++) {
        *(float4*)&outp[(l0+i)*64 + vA] = make_float4(m[i][0], m[i][1], m[i][2], m[i][3]);
        *(float4*)&outp[(l0+i)*64 + vB] = make_float4(m[i][4], m[i][5], m[i][6], m[i][7]);
    }
}

// ============================================================
// Kernel D2: combine 4 lf-quarter partial maxes, add q_att,
// gate/val dots, sigmoid/exp.
// ============================================================
__global__ void k_qfin(const float* __restrict__ gate_w,
                       const float* __restrict__ val_w,
                       const float* __restrict__ qmask,
                       float* __restrict__ out) {
    int blk = blockIdx.x;          // 256 = bwf(64) x lqt(4)
    int lqt = blk & 3;
    int bwf = blk >> 2;
    int b   = bwf >> 4;
    int lqbase = lqt * 32;
    int tid = threadIdx.x;         // 0..63
    int g  = tid & 7;
    int l0 = (tid >> 3) * 4;
    int vA = 4*g, vB = 32 + 4*g;

    float4 gwA = *(const float4*)&gate_w[vA];
    float4 gwB = *(const float4*)&gate_w[vB];
    float4 vwA = *(const float4*)&val_w[vA];
    float4 vwB = *(const float4*)&val_w[vB];

    const float* base = g_pmax + (size_t)blk * 4 * 2048;

    #pragma unroll
    for (int i = 0; i < 4; i++) {
        int row = l0 + i;
        float4 mA = *(const float4*)&base[row*64 + vA];
        float4 mB = *(const float4*)&base[row*64 + vB];
        #pragma unroll
        for (int q = 1; q < 4; q++) {
            float4 a = *(const float4*)&base[q*2048 + row*64 + vA];
            float4 bq = *(const float4*)&base[q*2048 + row*64 + vB];
            mA.x = fmaxf(mA.x, a.x);  mA.y = fmaxf(mA.y, a.y);
            mA.z = fmaxf(mA.z, a.z);  mA.w = fmaxf(mA.w, a.w);
            mB.x = fmaxf(mB.x, bq.x); mB.y = fmaxf(mB.y, bq.y);
            mB.z = fmaxf(mB.z, bq.z); mB.w = fmaxf(mB.w, bq.w);
        }
        int lq = lqbase + row;
        const float* qa = g_qatt + (size_t)(b*LQ + lq)*VV;
        float4 qaA = *(const float4*)&qa[vA];
        float4 qaB = *(const float4*)&qa[vB];
        mA.x += qaA.x; mA.y += qaA.y; mA.z += qaA.z; mA.w += qaA.w;
        mB.x += qaB.x; mB.y += qaB.y; mB.z += qaB.z; mB.w += qaB.w;

        float gs = mA.x*gwA.x + mA.y*gwA.y + mA.z*gwA.z + mA.w*gwA.w
                 + mB.x*gwB.x + mB.y*gwB.y + mB.z*gwB.z + mB.w*gwB.w;
        float vs = mA.x*vwA.x + mA.y*vwA.y + mA.z*vwA.z + mA.w*vwA.w
                 + mB.x*vwB.x + mB.y*vwB.y + mB.z*vwB.z + mB.w*vwB.w;
        #pragma unroll
        for (int off = 4; off >= 1; off >>= 1) {
            gs += __shfl_down_sync(0xffffffffu, gs, off, 8);
            vs += __shfl_down_sync(0xffffffffu, vs, off, 8);
        }
        if (g == 0) {
            float qm = qmask[b*LQ + lq];
            out[OUT_GATE + bwf*LQ + lq] = (1.f / (1.f + expf(-gs))) * qm;
            g_e2[bwf*LQ + lq] = expf(vs) * qm;
        }
    }
}

// ============================================================
// Kernel E: normalize e2 over LQ, query_code = sum_lq norm*q
// ============================================================
__global__ void k_qcode(const float* __restrict__ outq,
                        float* __restrict__ out) {
    int bwf = blockIdx.x;       // 0..63
    int b = bwf / WF;
    int t = threadIdx.x;        // 0..127 (d)
    __shared__ float esh[LQ];
    __shared__ float s_inv;
    esh[t] = g_e2[bwf*LQ + t];
    __syncthreads();
    if (t == 0) {
        float s = 0.f;
        for (int l = 0; l < LQ; l++) s += esh[l];
        s_inv = 1.f / (s + 1e-7f);
    }
    __syncthreads();
    float inv = s_inv;
    float acc = 0.f;
    #pragma unroll 8
    for (int l = 0; l < LQ; l++) acc += esh[l] * outq[((size_t)(b*LQ + l))*DD + t];
    out[OUT_QUERYCODE + bwf*DD + t] = acc * inv;
}

// ============================================================
extern "C" void kernel_launch(void* const* d_in, const int* in_sizes, int n_in,
                              void* d_out, int out_size) {
    const float* query    = (const float*)d_in[0];
    const float* fragment = (const float*)d_in[1];
    const float* qmask    = (const float*)d_in[2];
    const float* fmask    = (const float*)d_in[3];
    const float* projW    = (const float*)d_in[4];
    const float* projb    = (const float*)d_in[5];
    const float* saW      = (const float*)d_in[6];
    const float* qattW    = (const float*)d_in[7];
    const float* fattW    = (const float*)d_in[8];
    const float* qfW      = (const float*)d_in[9];
    const float* gatew    = (const float*)d_in[10];
    const float* valw     = (const float*)d_in[11];
    float* out = (float*)d_out;

    const int nrows = BB*LQ + BB*WF*LF;   // 4608

    const int smem = 13184 * (int)sizeof(float);   // 52736 B
    cudaFuncSetAttribute(k_qf, cudaFuncAttributeMaxDynamicSharedMemorySize, smem);

    k_proj<<<nrows, 128>>>(query, fragment, projW, projb, out + OUT_QUERY);
    k_fragcode<<<BB*WF, 128>>>(saW, fmask, out);
    k_att<<<nrows, 64>>>(out + OUT_QUERY, qattW, fattW);

    k_qf<<<1024, 128, smem>>>(qfW, out + OUT_QUERY);

    k_qfin<<<BB*WF*4, 64>>>(gatew, valw, qmask, out);
    k_qcode<<<BB*WF, 128>>>(out + OUT_QUERY, out);
}

// round 7
// speedup vs baseline: 3.9406x; 1.6847x over previous
#include <cuda_runtime.h>
#include <cuda_bf16.h>
#include <math.h>
#include <stdint.h>

#define BB 4
#define LQ 128
#define LF 64
#define NW 2
#define NFR 8
#define EE 128
#define DD 128
#define VV 64
#define WF (NW*NFR)   // 16

// ---- output layout (concatenated in reference tuple order) ----
#define OUT_FRAGCODE  0
#define OUT_QUERYCODE (BB*WF*DD)
#define OUT_SELFATT   (2*BB*WF*DD)
#define OUT_GATE      (2*BB*WF*DD + BB*WF*LF)
#define OUT_QUERY     (OUT_GATE + BB*WF*LQ)

// ---- scratch ----
__device__ float g_fproj[BB*WF*LF*DD];   // projected fragment (b,wf,lf,d)
__device__ float g_qatt [BB*LQ*VV];      // q_att (b,lq,v)
__device__ float g_fatt [BB*WF*LF*VV];   // f_att (b,wf,lf,v)
__device__ float g_pmax [512*64*64];     // partial maxes [bwf*8+lqh*4+lfq][64][64] (8MB)

// bf16 split helpers
__device__ __forceinline__ uint32_t pack_bf16x2(float lo_val, float hi_val) {
    // returns {hi_val<<16 | lo_val} as bf16x2 (element0 = lo_val, element1 = hi_val)
    uint32_t r;
    asm("cvt.rn.bf16x2.f32 %0, %1, %2;" : "=r"(r) : "f"(hi_val), "f"(lo_val));
    return r;
}
__device__ __forceinline__ float bf16lo_f32(uint32_t u) { return __uint_as_float(u << 16); }
__device__ __forceinline__ float bf16hi_f32(uint32_t u) { return __uint_as_float(u & 0xffff0000u); }

// split two fp32 into bf16x2 hi-word + bf16x2 lo-word
__device__ __forceinline__ void split2(float x0, float x1, uint32_t& hi, uint32_t& lo) {
    hi = pack_bf16x2(x0, x1);
    float r0 = x0 - bf16lo_f32(hi);
    float r1 = x1 - bf16hi_f32(hi);
    lo = pack_bf16x2(r0, r1);
}

// mma.sync m16n8k16 row.col f32.bf16.bf16.f32
__device__ __forceinline__ void mma16816(float* c, const uint32_t* a, const uint32_t* b) {
    asm volatile(
        "mma.sync.aligned.m16n8k16.row.col.f32.bf16.bf16.f32 "
        "{%0,%1,%2,%3}, {%4,%5,%6,%7}, {%8,%9}, {%0,%1,%2,%3};"
        : "+f"(c[0]), "+f"(c[1]), "+f"(c[2]), "+f"(c[3])
        : "r"(a[0]), "r"(a[1]), "r"(a[2]), "r"(a[3]), "r"(b[0]), "r"(b[1]));
}

// ============================================================
// Kernel A: fused projection + attention-weight GEMMs, tiled.
// grid 576 = 64 q-groups + 512 frag-groups, 8 rows each, 256 thr.
// (the all-zero-row mask in _project is a mathematical no-op)
// ============================================================
__global__ void __launch_bounds__(256) k_projatt(
    const float* __restrict__ query, const float* __restrict__ frag,
    const float* __restrict__ W, const float* __restrict__ bias,
    const float* __restrict__ qattW, const float* __restrict__ fattW,
    float* __restrict__ outq) {
    extern __shared__ float s[];
    float* Wsh  = s;            // 16384
    float* AWsh = s + 16384;    // 8192
    float* xsh  = s + 24576;    // 1024
    float* psh  = s + 25600;    // 1024   total 26624 floats
    int g = blockIdx.x;
    int tid = threadIdx.x;
    bool isq = (g < 64);

    {
        const float4* Wv = (const float4*)W;
        float4* Ws = (float4*)Wsh;
        #pragma unroll
        for (int i = 0; i < 16; i++) Ws[tid + 256*i] = Wv[tid + 256*i];
        const float4* Av = (const float4*)(isq ? qattW : fattW);
        float4* As = (float4*)AWsh;
        #pragma unroll
        for (int i = 0; i < 8; i++) As[tid + 256*i] = Av[tid + 256*i];
        const float* src = isq ? (query + (size_t)g*8*EE)
                               : (frag  + (size_t)(g-64)*8*EE);
        ((float4*)xsh)[tid] = ((const float4*)src)[tid];
    }
    __syncthreads();

    {
        int j = tid & 127, rh = tid >> 7;
        float bj = __ldg(&bias[j]);
        float a0 = bj, a1 = bj, a2 = bj, a3 = bj;
        #pragma unroll 4
        for (int d = 0; d < EE; d++) {
            float w = Wsh[d*DD + j];
            a0 = fmaf(xsh[(rh+0)*EE + d], w, a0);
            a1 = fmaf(xsh[(rh+2)*EE + d], w, a1);
            a2 = fmaf(xsh[(rh+4)*EE + d], w, a2);
            a3 = fmaf(xsh[(rh+6)*EE + d], w, a3);
        }
        psh[(rh+0)*DD + j] = a0; psh[(rh+2)*DD + j] = a1;
        psh[(rh+4)*DD + j] = a2; psh[(rh+6)*DD + j] = a3;
        float* dst = isq ? (outq + (size_t)g*8*DD)
                         : (g_fproj + (size_t)(g-64)*8*DD);
        dst[(rh+0)*DD + j] = a0; dst[(rh+2)*DD + j] = a1;
        dst[(rh+4)*DD + j] = a2; dst[(rh+6)*DD + j] = a3;
    }
    __syncthreads();

    {
        int j2 = tid & 63, r2 = tid >> 6;
        float a0 = 0.f, a1 = 0.f;
        #pragma unroll 4
        for (int d = 0; d < DD; d++) {
            float w = AWsh[d*VV + j2];
            a0 = fmaf(psh[(r2+0)*DD + d], w, a0);
            a1 = fmaf(psh[(r2+4)*DD + d], w, a1);
        }
        float* dst = isq ? (g_qatt + (size_t)g*8*VV)
                         : (g_fatt + (size_t)(g-64)*8*VV);
        dst[(r2+0)*VV + j2] = a0;
        dst[(r2+4)*VV + j2] = a1;
    }
}

// ============================================================
// Kernel B: fragment self-attention softmax + frag_code
// ============================================================
__global__ void k_fragcode(const float* __restrict__ saW,
                           const float* __restrict__ fmask,
                           float* __restrict__ out) {
    int bwf = blockIdx.x;
    int w = (bwf % WF) / NFR;
    const float* fbase = g_fproj + (size_t)bwf*LF*DD;
    __shared__ float att[LF];
    __shared__ float s_inv;
    int t = threadIdx.x;
    if (t < LF) {
        const float* fr = fbase + t*DD;
        const float* sw = saW + w*DD;
        float acc = 0.f;
        #pragma unroll 8
        for (int d = 0; d < DD; d++) acc += fr[d]*sw[d];
        att[t] = expf(acc) * fmask[bwf*LF + t];
    }
    __syncthreads();
    if (t == 0) {
        float ss = 0.f;
        for (int l = 0; l < LF; l++) ss += att[l];
        s_inv = 1.f / (ss + 1e-7f);
    }
    __syncthreads();
    float inv = s_inv;
    if (t < LF) out[OUT_SELFATT + bwf*LF + t] = att[t]*inv;
    float acc = 0.f;
    #pragma unroll 8
    for (int l = 0; l < LF; l++) acc += att[l]*inv*fbase[l*DD + t];
    out[OUT_FRAGCODE + bwf*DD + t] = acc;
}

// ============================================================
// Kernel C (hot, HMMA): per (bwf, lq-half64, lf-quarter16):
//   partial max over lf of (f_att + q @ (f_lf ⊙ W_qf))
// A = q 64x128 split bf16 hi/lo ONCE, fragments register-resident.
// Per lf: B' = f⊙W split hi/lo in smem; 3-pass split GEMM via
// mma.sync.m16n8k16 (Ahi·Bhi + Ahi·Blo + Alo·Bhi), fp32 accum.
// 8 warps: warp = (m-strip 16 of 64) x (n-half 32 of 64).
// ============================================================
// smem word offsets
#define QW_WT   0                      // W transposed [64][130] = 8320
#define QW_AH   8320                   // [64][68] u32 = 4352
#define QW_AL   (QW_AH + 4352)
#define QW_BH   (QW_AL + 4352)         // [64][68] u32 = 4352
#define QW_BL   (QW_BH + 4352)
#define QW_TOT  (QW_BL + 4352)         // 25728 words = 102912 B

__global__ void __launch_bounds__(256) k_qf_mma(
    const float* __restrict__ qfW, const float* __restrict__ outq) {
    extern __shared__ float s[];
    float* Wt = s + QW_WT;                       // [v][130] fp32
    uint32_t* Ah = (uint32_t*)(s + QW_AH);       // [row][68]
    uint32_t* Al = (uint32_t*)(s + QW_AL);
    uint32_t* Bh = (uint32_t*)(s + QW_BH);       // [v][68]
    uint32_t* Bl = (uint32_t*)(s + QW_BL);

    int blk = blockIdx.x;            // 512 = bwf(64) x lqh(2) x lfq(4)
    int lfq = blk & 3;
    int lqh = (blk >> 2) & 1;
    int bwf = blk >> 3;
    int b = bwf >> 4;
    int lfbase = lfq * 16;
    int tid = threadIdx.x, lane = tid & 31, wid = tid >> 5;
    int m0 = (wid & 3) * 16;         // m-strip within 64
    int n0 = (wid >> 2) * 32;        // n-half

    // stage W transposed: Wt[v][d]
    for (int idx = tid; idx < DD*VV; idx += 256) {
        int d = idx >> 6, v = idx & 63;
        Wt[v*130 + d] = qfW[idx];
    }
    // convert A (q tile 64x128) -> bf16 hi/lo words [row][68]
    for (int idx = tid; idx < 64*64; idx += 256) {
        int row = idx >> 6, cp = idx & 63;
        float2 qv = *(const float2*)&outq[((size_t)(b*LQ + lqh*64 + row))*DD + cp*2];
        uint32_t hi, lo;
        split2(qv.x, qv.y, hi, lo);
        Ah[row*68 + cp] = hi;
        Al[row*68 + cp] = lo;
    }
    __syncthreads();

    // load A fragments (register-resident for all lf)
    uint32_t ah[8][4], al[8][4];
    {
        int r = m0 + (lane >> 2);
        #pragma unroll
        for (int k = 0; k < 8; k++) {
            int c = k*8 + (lane & 3);
            ah[k][0] = Ah[r*68 + c];       ah[k][1] = Ah[(r+8)*68 + c];
            ah[k][2] = Ah[r*68 + c + 4];   ah[k][3] = Ah[(r+8)*68 + c + 4];
            al[k][0] = Al[r*68 + c];       al[k][1] = Al[(r+8)*68 + c];
            al[k][2] = Al[r*68 + c + 4];   al[k][3] = Al[(r+8)*68 + c + 4];
        }
    }

    float mx[4][4];
    #pragma unroll
    for (int t = 0; t < 4; t++)
        #pragma unroll
        for (int i = 0; i < 4; i++) mx[t][i] = -INFINITY;

    for (int k16 = 0; k16 < 16; k16++) {
        int lf = lfbase + k16;
        __syncthreads();     // prior-iter B reads complete before overwrite

        // convert B' = f ⊙ W -> bf16 hi/lo [v][68]
        const float* fptr = g_fproj + ((size_t)bwf*LF + lf)*DD;
        for (int idx = tid; idx < 64*64; idx += 256) {
            int v = idx >> 6, cp = idx & 63;
            float2 wv = *(const float2*)&Wt[v*130 + cp*2];
            float2 fv = *(const float2*)&fptr[cp*2];
            uint32_t hi, lo;
            split2(wv.x*fv.x, wv.y*fv.y, hi, lo);
            Bh[v*68 + cp] = hi;
            Bl[v*68 + cp] = lo;
        }
        __syncthreads();

        // 3-pass split GEMM, C[16x32] per warp
        float cc[4][4];
        #pragma unroll
        for (int t = 0; t < 4; t++)
            #pragma unroll
            for (int i = 0; i < 4; i++) cc[t][i] = 0.f;

        #pragma unroll
        for (int k = 0; k < 8; k++) {
            #pragma unroll
            for (int t = 0; t < 4; t++) {
                int v = n0 + t*8 + (lane >> 2);
                int c = k*8 + (lane & 3);
                uint32_t bh[2], bl[2];
                bh[0] = Bh[v*68 + c];  bh[1] = Bh[v*68 + c + 4];
                bl[0] = Bl[v*68 + c];  bl[1] = Bl[v*68 + c + 4];
                mma16816(cc[t], ah[k], bh);
                mma16816(cc[t], ah[k], bl);
                mma16816(cc[t], al[k], bh);
            }
        }

        // running max of (cc + f_att)
        const float* fa = g_fatt + ((size_t)bwf*LF + lf)*VV;
        #pragma unroll
        for (int t = 0; t < 4; t++) {
            int col = n0 + t*8 + (lane & 3)*2;
            float2 f2 = *(const float2*)&fa[col];
            mx[t][0] = fmaxf(mx[t][0], cc[t][0] + f2.x);
            mx[t][1] = fmaxf(mx[t][1], cc[t][1] + f2.y);
            mx[t][2] = fmaxf(mx[t][2], cc[t][2] + f2.x);
            mx[t][3] = fmaxf(mx[t][3], cc[t][3] + f2.y);
        }
    }

    // write partial-max tile [64][64]
    float* outp = g_pmax + (size_t)blk * 4096;
    int r0 = m0 + (lane >> 2);
    #pragma unroll
    for (int t = 0; t < 4; t++) {
        int col = n0 + t*8 + (lane & 3)*2;
        *(float2*)&outp[r0*64 + col]     = make_float2(mx[t][0], mx[t][1]);
        *(float2*)&outp[(r0+8)*64 + col] = make_float2(mx[t][2], mx[t][3]);
    }
}

// ============================================================
// Kernel D: finalize — combine 4 lf-quarters, + q_att, gate/val dots,
// sigmoid/exp, softmax over LQ, query_code.  grid 64 (bwf), 128 thr.
// ============================================================
__global__ void k_fin(const float* __restrict__ gate_w,
                      const float* __restrict__ val_w,
                      const float* __restrict__ qmask,
                      const float* __restrict__ outq,
                      float* __restrict__ out) {
    int bwf = blockIdx.x;
    int b = bwf >> 4;
    int t = threadIdx.x;     // lq in phase 1, d in phase 2
    __shared__ float esh[LQ];
    __shared__ float s_inv;

    {
        int lqh = t >> 6, r = t & 63;
        const float* base = g_pmax + ((size_t)(bwf*8 + lqh*4)) * 4096 + r*64;
        float gs = 0.f, vs = 0.f;
        const float4* qa = (const float4*)(g_qatt + (size_t)(b*LQ + t)*VV);
        const float4* gw = (const float4*)gate_w;
        const float4* vw = (const float4*)val_w;
        #pragma unroll
        for (int i = 0; i < 16; i++) {
            float4 a0 = *(const float4*)&base[i*4];
            float4 a1 = *(const float4*)&base[4096 + i*4];
            float4 a2 = *(const float4*)&base[2*4096 + i*4];
            float4 a3 = *(const float4*)&base[3*4096 + i*4];
            float4 q = qa[i], g4 = gw[i], v4 = vw[i];
            float mxv = fmaxf(fmaxf(a0.x, a1.x), fmaxf(a2.x, a3.x)) + q.x;
            float myv = fmaxf(fmaxf(a0.y, a1.y), fmaxf(a2.y, a3.y)) + q.y;
            float mzv = fmaxf(fmaxf(a0.z, a1.z), fmaxf(a2.z, a3.z)) + q.z;
            float mwv = fmaxf(fmaxf(a0.w, a1.w), fmaxf(a2.w, a3.w)) + q.w;
            gs += mxv*g4.x + myv*g4.y + mzv*g4.z + mwv*g4.w;
            vs += mxv*v4.x + myv*v4.y + mzv*v4.z + mwv*v4.w;
        }
        float qm = qmask[b*LQ + t];
        out[OUT_GATE + bwf*LQ + t] = (1.f / (1.f + expf(-gs))) * qm;
        esh[t] = expf(vs) * qm;
    }
    __syncthreads();
    if (t == 0) {
        float ss = 0.f;
        for (int l = 0; l < LQ; l++) ss += esh[l];
        s_inv = 1.f / (ss + 1e-7f);
    }
    __syncthreads();
    float inv = s_inv;
    float acc = 0.f;
    #pragma unroll 8
    for (int l = 0; l < LQ; l++) acc += esh[l] * outq[((size_t)(b*LQ + l))*DD + t];
    out[OUT_QUERYCODE + bwf*DD + t] = acc * inv;
}

// ============================================================
extern "C" void kernel_launch(void* const* d_in, const int* in_sizes, int n_in,
                              void* d_out, int out_size) {
    const float* query    = (const float*)d_in[0];
    const float* fragment = (const float*)d_in[1];
    const float* qmask    = (const float*)d_in[2];
    const float* fmask    = (const float*)d_in[3];
    const float* projW    = (const float*)d_in[4];
    const float* projb    = (const float*)d_in[5];
    const float* saW      = (const float*)d_in[6];
    const float* qattW    = (const float*)d_in[7];
    const float* fattW    = (const float*)d_in[8];
    const float* qfW      = (const float*)d_in[9];
    const float* gatew    = (const float*)d_in[10];
    const float* valw     = (const float*)d_in[11];
    float* out = (float*)d_out;
    float* outq = out + OUT_QUERY;

    const int smemPA = 26624 * (int)sizeof(float);   // 106496
    const int smemQF = QW_TOT * (int)sizeof(float);  // 102912
    cudaFuncSetAttribute(k_projatt, cudaFuncAttributeMaxDynamicSharedMemorySize, smemPA);
    cudaFuncSetAttribute(k_qf_mma, cudaFuncAttributeMaxDynamicSharedMemorySize, smemQF);

    k_projatt<<<576, 256, smemPA>>>(query, fragment, projW, projb, qattW, fattW, outq);
    k_fragcode<<<BB*WF, 128>>>(saW, fmask, out);
    k_qf_mma<<<512, 256, smemQF>>>(qfW, outq);
    k_fin<<<BB*WF, 128>>>(gatew, valw, qmask, outq, out);
}